// round 12
// baseline (speedup 1.0000x reference)
#include <cuda_runtime.h>
#include <cuda_bf16.h>
#include <cstdint>

// Problem constants (reference: TRACK_SIZE=16, C=240 -> 15 tracks).
#define C_TOT   240
#define ROW32   30          // 32B (8-float) chunks per row
#define TJ      32          // input rows per tile
#define TY      8           // blockDim.y
#define NCTA    912         // persistent grid: 152 SMs x 6 CTAs

// 256-bit global load (non-coherent) / store, sm_103a.
__device__ __forceinline__ void ldg256(const float* p, float* f) {
    asm volatile("ld.global.nc.v8.f32 {%0,%1,%2,%3,%4,%5,%6,%7}, [%8];"
                 : "=f"(f[0]), "=f"(f[1]), "=f"(f[2]), "=f"(f[3]),
                   "=f"(f[4]), "=f"(f[5]), "=f"(f[6]), "=f"(f[7])
                 : "l"(p));
}
__device__ __forceinline__ void stg256(float* p, const float* f) {
    asm volatile("st.global.v8.f32 [%0], {%1,%2,%3,%4,%5,%6,%7,%8};"
                 :: "l"(p),
                    "f"(f[0]), "f"(f[1]), "f"(f[2]), "f"(f[3]),
                    "f"(f[4]), "f"(f[5]), "f"(f[6]), "f"(f[7])
                 : "memory");
}

// Persistent input-major scatter at 32B/lane granularity (R10 champion
// structure, grid-stride over tiles to kill wave transitions):
// each tile reads input rows [r0, r0+32) fully coalesced (LDG.256; rows
// >= L skipped), then scatters each 32B chunk to its 1-3 output positions.
// Forward map: out[j][t] = x[((j+shift_t)%P)%L][t]; inverse: for vv in
// {r, r+L, r+2L} with vv<P: j = vv-shift (and j+P for the P-wrap case).
__global__ __launch_bounds__(240, 6) void rc_scatter256p_kernel(
    const float* __restrict__ x,        // (B, N, 240)
    const int*   __restrict__ lengths,  // (B,)
    float*       __restrict__ out,      // (B, max_len, 240)
    int B, int N, int max_len, int tiles_x)
{
    // min(lengths): B tiny; L1-hit broadcast loads. Once per CTA.
    int minL = __ldg(lengths);
    #pragma unroll 4
    for (int i = 1; i < B; ++i) minL = min(minL, __ldg(lengths + i));
    const int P = 3 * minL;

    const int q2 = threadIdx.x;          // 0..29 : 32B chunk within row
    const int ty = threadIdx.y;          // 0..7
    const int shift = (1u << (q2 >> 1)) >> 1;   // track = q2/2

    const int ntiles = tiles_x * B;

    for (int tile = blockIdx.x; tile < ntiles; tile += NCTA) {
        const int b  = tile / tiles_x;
        const int bx = tile - b * tiles_x;
        const int r0 = bx * TJ;
        const int L  = __ldg(lengths + b);
        if (r0 >= L) continue;           // rows >= L are never used

        const float* __restrict__ src =
            x + ((size_t)b * N + r0) * C_TOT + q2 * 8;
        float* __restrict__ dst =
            out + (size_t)b * max_len * C_TOT + q2 * 8;

        // Two batches of 2 rows: 2 LDG.256 in flight, then scatter.
        #pragma unroll
        for (int h = 0; h < 2; ++h) {
            float fa[8], fb[8];
            const int rla = ty + 16 * h;      // rows ty, ty+16
            const int rlb = rla + 8;          // rows ty+8, ty+24
            const int ra = r0 + rla, rb = r0 + rlb;
            const bool oka = ra < L, okb = rb < L;
            if (oka) ldg256(src + (size_t)rla * C_TOT, fa);
            if (okb) ldg256(src + (size_t)rlb * C_TOT, fb);

            #pragma unroll
            for (int s = 0; s < 2; ++s) {
                const int r = s ? rb : ra;
                const float* f = s ? fb : fa;
                if (!(s ? okb : oka)) continue;
                #pragma unroll
                for (int m = 0; m < 3; ++m) {
                    const int vv = r + m * L;
                    if (vv < P) {
                        const int j = vv - shift;
                        if (j >= 0 && j < max_len)
                            stg256(dst + (size_t)j * C_TOT, f);
                        const int j2 = j + P;   // P-wrap generality
                        if (j2 >= 0 && j2 < max_len)
                            stg256(dst + (size_t)j2 * C_TOT, f);
                    }
                }
            }
        }
    }
}

extern "C" void kernel_launch(void* const* d_in, const int* in_sizes, int n_in,
                              void* d_out, int out_size) {
    const float* x       = (const float*)d_in[0];
    const int*   lengths = (const int*)d_in[1];
    float*       out     = (float*)d_out;

    const int B = in_sizes[1];                    // 8
    const int N = in_sizes[0] / (B * C_TOT);      // 16384
    const int max_len = out_size / (B * C_TOT);   // max(lengths)
    const int tiles_x = (N + TJ - 1) / TJ;        // 512

    dim3 blk(ROW32, TY, 1);                       // 240 threads
    rc_scatter256p_kernel<<<NCTA, blk>>>(x, lengths, out,
                                         B, N, max_len, tiles_x);
}

// round 13
// speedup vs baseline: 1.0976x; 1.0976x over previous
#include <cuda_runtime.h>
#include <cuda_bf16.h>
#include <cstdint>

// Problem constants (reference: TRACK_SIZE=16, C=240 -> 15 tracks).
#define C_TOT   240
#define ROW32   30          // 32B (8-float) chunks per row
#define TJ      32          // input rows per CTA tile
#define TY      8           // blockDim.y

// 256-bit global load, non-coherent, L2 evict-last (pin x in L2).
__device__ __forceinline__ void ldg256_el(const float* p, float* f) {
    asm volatile("ld.global.nc.L2::evict_last.v8.f32 "
                 "{%0,%1,%2,%3,%4,%5,%6,%7}, [%8];"
                 : "=f"(f[0]), "=f"(f[1]), "=f"(f[2]), "=f"(f[3]),
                   "=f"(f[4]), "=f"(f[5]), "=f"(f[6]), "=f"(f[7])
                 : "l"(p));
}
// 256-bit global store, L2 evict-first (write stream never claims L2).
__device__ __forceinline__ void stg256_ef(float* p, const float* f) {
    asm volatile("st.global.L2::evict_first.v8.f32 "
                 "[%0], {%1,%2,%3,%4,%5,%6,%7,%8};"
                 :: "l"(p),
                    "f"(f[0]), "f"(f[1]), "f"(f[2]), "f"(f[3]),
                    "f"(f[4]), "f"(f[5]), "f"(f[6]), "f"(f[7])
                 : "memory");
}

// Input-major scatter at 32B/lane granularity (champion R10 structure):
// CTA reads input rows [r0, r0+32) fully coalesced (LDG.256; rows >= L
// skipped), then scatters each 32B chunk to its 1-3 output positions.
// Forward map: out[j][t] = x[((j+shift_t)%P)%L][t]; inverse: for vv in
// {r, r+L, r+2L} with vv<P: j = vv-shift (and j+P for the P-wrap case).
// R13 delta: L2 policy pair (evict_last reads / evict_first writes) to keep
// x resident in the 126MB L2 and cut the ~31MB of DRAM read misses.
__global__ __launch_bounds__(240, 6) void rc_scatter256_kernel(
    const float* __restrict__ x,        // (B, N, 240)
    const int*   __restrict__ lengths,  // (B,)
    float*       __restrict__ out,      // (B, max_len, 240)
    int B, int N, int max_len)
{
    const int b  = blockIdx.z;
    const int L  = __ldg(lengths + b);
    const int r0 = blockIdx.x * TJ;
    if (r0 >= L) return;                 // rows >= L are never used

    // min(lengths): B tiny; L1-hit broadcast loads.
    int minL = __ldg(lengths);
    #pragma unroll 4
    for (int i = 1; i < B; ++i) minL = min(minL, __ldg(lengths + i));
    const int P = 3 * minL;

    const int q2 = threadIdx.x;          // 0..29 : 32B chunk within row
    const int ty = threadIdx.y;          // 0..7
    const int shift = (1u << (q2 >> 1)) >> 1;   // track = q2/2

    const float* __restrict__ src = x + ((size_t)b * N + r0) * C_TOT + q2 * 8;
    float* __restrict__ dst = out + (size_t)b * max_len * C_TOT + q2 * 8;

    // Two batches of 2 rows: 2 LDG.256 in flight, then scatter, repeat.
    #pragma unroll
    for (int h = 0; h < 2; ++h) {
        float fa[8], fb[8];
        const int rla = ty + 16 * h;          // rows ty, ty+16
        const int rlb = rla + 8;              // rows ty+8, ty+24
        const int ra = r0 + rla, rb = r0 + rlb;
        const bool oka = ra < L, okb = rb < L;
        if (oka) ldg256_el(src + (size_t)rla * C_TOT, fa);
        if (okb) ldg256_el(src + (size_t)rlb * C_TOT, fb);

        #pragma unroll
        for (int s = 0; s < 2; ++s) {
            const int r = s ? rb : ra;
            const float* f = s ? fb : fa;
            if (!(s ? okb : oka)) continue;
            #pragma unroll
            for (int m = 0; m < 3; ++m) {
                const int vv = r + m * L;
                if (vv < P) {
                    const int j = vv - shift;
                    if (j >= 0 && j < max_len)
                        stg256_ef(dst + (size_t)j * C_TOT, f);
                    const int j2 = j + P;     // P-wrap generality
                    if (j2 >= 0 && j2 < max_len)
                        stg256_ef(dst + (size_t)j2 * C_TOT, f);
                }
            }
        }
    }
}

extern "C" void kernel_launch(void* const* d_in, const int* in_sizes, int n_in,
                              void* d_out, int out_size) {
    const float* x       = (const float*)d_in[0];
    const int*   lengths = (const int*)d_in[1];
    float*       out     = (float*)d_out;

    const int B = in_sizes[1];                    // 8
    const int N = in_sizes[0] / (B * C_TOT);      // 16384
    const int max_len = out_size / (B * C_TOT);   // max(lengths)

    dim3 blk(ROW32, TY, 1);                       // 240 threads
    dim3 grid((N + TJ - 1) / TJ, 1, B);           // (512,1,8); tail CTAs exit
    rc_scatter256_kernel<<<grid, blk>>>(x, lengths, out, B, N, max_len);
}

// round 14
// speedup vs baseline: 1.0985x; 1.0009x over previous
#include <cuda_runtime.h>
#include <cuda_bf16.h>
#include <cstdint>

// Problem constants (reference: TRACK_SIZE=16, C=240 -> 15 tracks).
#define C_TOT   240
#define ROW32   30          // 32B (8-float) chunks per row
#define TJ      32          // input rows per CTA tile
#define TY      8           // blockDim.y

// 256-bit global load (non-coherent) / store, sm_103a.
__device__ __forceinline__ void ldg256(const float* p, float* f) {
    asm volatile("ld.global.nc.v8.f32 {%0,%1,%2,%3,%4,%5,%6,%7}, [%8];"
                 : "=f"(f[0]), "=f"(f[1]), "=f"(f[2]), "=f"(f[3]),
                   "=f"(f[4]), "=f"(f[5]), "=f"(f[6]), "=f"(f[7])
                 : "l"(p));
}
__device__ __forceinline__ void stg256(float* p, const float* f) {
    asm volatile("st.global.v8.f32 [%0], {%1,%2,%3,%4,%5,%6,%7,%8};"
                 :: "l"(p),
                    "f"(f[0]), "f"(f[1]), "f"(f[2]), "f"(f[3]),
                    "f"(f[4]), "f"(f[5]), "f"(f[6]), "f"(f[7])
                 : "memory");
}

// Input-major scatter at 32B/lane granularity (champion R10 structure):
// CTA reads input rows [r0, r0+32) fully coalesced (LDG.256; rows >= L
// skipped), then scatters each 32B chunk to its 1-3 output positions.
// Forward map: out[j][t] = x[((j+shift_t)%P)%L][t]; inverse: for vv in
// {r, r+L, r+2L} with vv<P: j = vv-shift (and j+P for the P-wrap case).
// R14 delta: all 4 LDG.256 front-batched (MLP=4 before the store burst).
__global__ __launch_bounds__(240, 4) void rc_scatter256_kernel(
    const float* __restrict__ x,        // (B, N, 240)
    const int*   __restrict__ lengths,  // (B,)
    float*       __restrict__ out,      // (B, max_len, 240)
    int B, int N, int max_len)
{
    const int b  = blockIdx.z;
    const int L  = __ldg(lengths + b);
    const int r0 = blockIdx.x * TJ;
    if (r0 >= L) return;                 // rows >= L are never used

    // min(lengths): B tiny; L1-hit broadcast loads.
    int minL = __ldg(lengths);
    #pragma unroll 4
    for (int i = 1; i < B; ++i) minL = min(minL, __ldg(lengths + i));
    const int P = 3 * minL;

    const int q2 = threadIdx.x;          // 0..29 : 32B chunk within row
    const int ty = threadIdx.y;          // 0..7
    const int shift = (1u << (q2 >> 1)) >> 1;   // track = q2/2

    const float* __restrict__ src = x + ((size_t)b * N + r0) * C_TOT + q2 * 8;
    float* __restrict__ dst = out + (size_t)b * max_len * C_TOT + q2 * 8;

    // Phase 1: all 4 LDG.256 front-batched — loads hit the L1tex queue
    // before any store-issue burst; full read MLP during the write drain.
    float f[4][8];
    int   rr[4];
    bool  ok[4];
    #pragma unroll
    for (int k = 0; k < 4; ++k) {
        const int rl = ty + 8 * k;       // rows ty, ty+8, ty+16, ty+24
        rr[k] = r0 + rl;
        ok[k] = rr[k] < L;
        if (ok[k]) ldg256(src + (size_t)rl * C_TOT, f[k]);
    }

    // Phase 2: scatter each chunk to its output positions.
    #pragma unroll
    for (int k = 0; k < 4; ++k) {
        if (!ok[k]) continue;
        const int r = rr[k];
        #pragma unroll
        for (int m = 0; m < 3; ++m) {
            const int vv = r + m * L;
            if (vv < P) {
                const int j = vv - shift;
                if (j >= 0 && j < max_len)
                    stg256(dst + (size_t)j * C_TOT, f[k]);
                const int j2 = j + P;     // P-wrap generality
                if (j2 >= 0 && j2 < max_len)
                    stg256(dst + (size_t)j2 * C_TOT, f[k]);
            }
        }
    }
}

extern "C" void kernel_launch(void* const* d_in, const int* in_sizes, int n_in,
                              void* d_out, int out_size) {
    const float* x       = (const float*)d_in[0];
    const int*   lengths = (const int*)d_in[1];
    float*       out     = (float*)d_out;

    const int B = in_sizes[1];                    // 8
    const int N = in_sizes[0] / (B * C_TOT);      // 16384
    const int max_len = out_size / (B * C_TOT);   // max(lengths)

    dim3 blk(ROW32, TY, 1);                       // 240 threads
    dim3 grid((N + TJ - 1) / TJ, 1, B);           // (512,1,8); tail CTAs exit
    rc_scatter256_kernel<<<grid, blk>>>(x, lengths, out, B, N, max_len);
}